// round 15
// baseline (speedup 1.0000x reference)
#include <cuda_runtime.h>
#include <cuda_fp16.h>

#define IN_C   256
#define HC     256
#define HEADS  4
#define CPH    64
#define HC2    128          // half2 count per row
#define NMAX   10000
#define EMAX   320000
#define ETMAX  (EMAX + NMAX)
#define NEG_SLOPE 0.2f
#define LN_EPS 1e-5f

// ---------------- scratch (static device memory; no allocations) -------------
__device__ __align__(16) __half2 g_hh[NMAX * HC2]; // GAT features (fp16 pairs)
__device__ __align__(16) __half  g_xh[NMAX * IN_C]; // X in fp16
__device__ __align__(16) __half  g_wh[IN_C * HC];   // W_gat in fp16 (k-major)
__device__ float  g_als[NMAX * HEADS];
__device__ float  g_ald[NMAX * HEADS];
__device__ __align__(16) int g_deg[NMAX];          // zero at load + re-zeroed by k_gcn
__device__ int    g_off[NMAX + 1];
__device__ int    g_cur[NMAX];
__device__ int    g_esrc[ETMAX];       // CSR by dst: src node of each in-edge
__device__ float2 g_dh[NMAX];          // {dinv, h2} packed

// ---------------- CSR construction -------------------------------------------
__global__ void k_count(const int* __restrict__ dst, int E) {
    int i0 = (blockIdx.x * blockDim.x + threadIdx.x) * 4;
    if (i0 + 3 < E) {
        int4 d4 = *(const int4*)(dst + i0);
        atomicAdd(&g_deg[d4.x], 1);
        atomicAdd(&g_deg[d4.y], 1);
        atomicAdd(&g_deg[d4.z], 1);
        atomicAdd(&g_deg[d4.w], 1);
    } else {
        for (int j = 0; j < 4; j++) {
            int i = i0 + j;
            if (i < E) atomicAdd(&g_deg[dst[i]], 1);
        }
    }
}

// single-block exclusive scan of (g_deg + 1) -> g_off / g_cur, 4 elems/thread
__global__ void k_scan(int N) {
    __shared__ int warp_sums[32];
    __shared__ int carry_s;
    int tid = threadIdx.x;
    int lane = tid & 31, wid = tid >> 5;
    if (tid == 0) carry_s = 0;
    __syncthreads();
    for (int base = 0; base < N; base += 4096) {
        int i0 = base + tid * 4;
        int v0 = 0, v1 = 0, v2 = 0, v3 = 0;
        if (i0 + 3 < N) {
            int4 dv = *(const int4*)&g_deg[i0];
            v0 = dv.x + 1; v1 = dv.y + 1; v2 = dv.z + 1; v3 = dv.w + 1;
        } else {
            if (i0     < N) v0 = g_deg[i0]     + 1;
            if (i0 + 1 < N) v1 = g_deg[i0 + 1] + 1;
            if (i0 + 2 < N) v2 = g_deg[i0 + 2] + 1;
            if (i0 + 3 < N) v3 = g_deg[i0 + 3] + 1;
        }
        int v = v0 + v1 + v2 + v3;
        int incl = v;
#pragma unroll
        for (int s = 1; s < 32; s <<= 1) {
            int t = __shfl_up_sync(0xffffffffu, incl, s);
            if (lane >= s) incl += t;
        }
        if (lane == 31) warp_sums[wid] = incl;
        __syncthreads();
        if (wid == 0) {
            int w = warp_sums[lane];
#pragma unroll
            for (int s = 1; s < 32; s <<= 1) {
                int t = __shfl_up_sync(0xffffffffu, w, s);
                if (lane >= s) w += t;
            }
            warp_sums[lane] = w;
        }
        __syncthreads();
        int warp_base = (wid > 0) ? warp_sums[wid - 1] : 0;
        int c = carry_s;
        int incl_blk = warp_base + incl;
        int e0 = c + incl_blk - v;
        int e1 = e0 + v0, e2 = e1 + v1, e3 = e2 + v2;
        if (i0     < N) { g_off[i0]     = e0; g_cur[i0]     = e0; if (i0     == N - 1) g_off[N] = e1; }
        if (i0 + 1 < N) { g_off[i0 + 1] = e1; g_cur[i0 + 1] = e1; if (i0 + 1 == N - 1) g_off[N] = e2; }
        if (i0 + 2 < N) { g_off[i0 + 2] = e2; g_cur[i0 + 2] = e2; if (i0 + 2 == N - 1) g_off[N] = e3; }
        if (i0 + 3 < N) { g_off[i0 + 3] = e3; g_cur[i0 + 3] = e3; if (i0 + 3 == N - 1) g_off[N] = e3 + v3; }
        __syncthreads();
        if (tid == 1023) carry_s = c + incl_blk;
        __syncthreads();
    }
}

__global__ void k_scatter(const int* __restrict__ src, const int* __restrict__ dst,
                          int E, int N) {
    int i0 = (blockIdx.x * blockDim.x + threadIdx.x) * 4;
    if (i0 + 3 < E) {
        int4 s4 = *(const int4*)(src + i0);
        int4 d4 = *(const int4*)(dst + i0);
        int p0 = atomicAdd(&g_cur[d4.x], 1);
        int p1 = atomicAdd(&g_cur[d4.y], 1);
        int p2 = atomicAdd(&g_cur[d4.z], 1);
        int p3 = atomicAdd(&g_cur[d4.w], 1);
        g_esrc[p0] = s4.x; g_esrc[p1] = s4.y;
        g_esrc[p2] = s4.z; g_esrc[p3] = s4.w;
    } else {
        for (int j = 0; j < 4; j++) {
            int i = i0 + j;
            if (i >= E + N) break;
            int d, s;
            if (i < E) { d = dst[i]; s = src[i]; }
            else       { d = i - E;  s = i - E;  }   // self loop
            int pos = atomicAdd(&g_cur[d], 1);
            g_esrc[pos] = s;
        }
    }
}

// ---------------- fp32 -> fp16 convert for X and W (1 chunk/thread) -----------
__global__ void k_half(const float* __restrict__ X, const float* __restrict__ W, int N) {
    int t = blockIdx.x * 256 + threadIdx.x;      // 8 elems per thread
    int nx = N * (IN_C / 8);
    const float* sp;
    __half* dp;
    if (t < nx) {
        sp = X + (long)t * 8;
        dp = g_xh + (long)t * 8;
    } else {
        int u = t - nx;
        if (u >= IN_C * HC / 8) return;
        sp = W + (long)u * 8;
        dp = g_wh + (long)u * 8;
    }
    float4 a = *(const float4*)sp;
    float4 b = *(const float4*)(sp + 4);
    __half2 h[4];
    h[0] = __floats2half2_rn(a.x, a.y);
    h[1] = __floats2half2_rn(a.z, a.w);
    h[2] = __floats2half2_rn(b.x, b.y);
    h[3] = __floats2half2_rn(b.z, b.w);
    *(uint4*)dp = *(uint4*)h;
}

// ---------------- tensor-core GEMM + fused logits + fp16 h store --------------
__device__ __forceinline__ void mma16816(float* c, const unsigned* a, const unsigned* b) {
    asm volatile("mma.sync.aligned.m16n8k16.row.col.f32.f16.f16.f32 "
                 "{%0,%1,%2,%3}, {%4,%5,%6,%7}, {%8,%9}, {%0,%1,%2,%3};"
                 : "+f"(c[0]), "+f"(c[1]), "+f"(c[2]), "+f"(c[3])
                 : "r"(a[0]), "r"(a[1]), "r"(a[2]), "r"(a[3]),
                   "r"(b[0]), "r"(b[1]));
}

__device__ __forceinline__ void cp16(unsigned dst, const void* src, int src_sz) {
    asm volatile("cp.async.cg.shared.global [%0], [%1], 16, %2;"
                 :: "r"(dst), "l"(__cvta_generic_to_global(src)), "r"(src_sz));
}

__global__ void __launch_bounds__(128) k_gemm(const float* __restrict__ asrc,
                                              const float* __restrict__ adst,
                                              int N) {
    __shared__ __align__(16) __half As[2][64 * 64];
    __shared__ __align__(16) __half Bs[2][64 * 64];
    __shared__ float part_s[64], part_d[64];
    int tid = threadIdx.x;
    int lane = tid & 31, w = tid >> 5;
    int wm = w >> 1, wn = w & 1;
    int head = blockIdx.x;
    int mblk = blockIdx.y * 64;
    unsigned asb = (unsigned)__cvta_generic_to_shared(&As[0][0]);
    unsigned bsb = (unsigned)__cvta_generic_to_shared(&Bs[0][0]);

    int lr = tid >> 1;
    int lcu = (tid & 1) * 4;
    int arow = mblk + lr;
    int asz = (arow < N) ? 16 : 0;
    const __half* pa = g_xh + (long)min(arow, N - 1) * IN_C + lcu * 8;
    const __half* pb = g_wh + (long)lr * HC + head * 64 + lcu * 8;

    float c[2][4][4];
#pragma unroll
    for (int i = 0; i < 2; i++)
#pragma unroll
        for (int j = 0; j < 4; j++)
#pragma unroll
            for (int q = 0; q < 4; q++) c[i][j][q] = 0.f;

    auto load_slice = [&](int s, int buf) {
        unsigned ab = asb + buf * 8192;
        unsigned bb = bsb + buf * 8192;
#pragma unroll
        for (int u = 0; u < 4; u++) {
            int cc = lcu + u;
            int unit = lr * 8 + (cc ^ (lr & 7));
            cp16(ab + unit * 16, pa + s * 64 + u * 8, asz);
            cp16(bb + unit * 16, pb + (long)s * 64 * HC + u * 8, 16);
        }
    };

    load_slice(0, 0);
    asm volatile("cp.async.commit_group;");

    for (int s = 0; s < 4; s++) {
        if (s < 3) {
            load_slice(s + 1, (s + 1) & 1);
            asm volatile("cp.async.commit_group;");
            asm volatile("cp.async.wait_group 1;");
        } else {
            asm volatile("cp.async.wait_group 0;");
        }
        __syncthreads();

        unsigned ab = asb + (s & 1) * 8192;
        unsigned bb = bsb + (s & 1) * 8192;
#pragma unroll
        for (int kk = 0; kk < 4; kk++) {
            unsigned af[2][4], bf[4][2];
#pragma unroll
            for (int i = 0; i < 2; i++) {
                int r = wm * 32 + i * 16 + (lane & 15);
                int cc = 2 * kk + (lane >> 4);
                int unit = r * 8 + (cc ^ (r & 7));
                unsigned addr = ab + unit * 16;
                asm volatile("ldmatrix.sync.aligned.m8n8.x4.shared.b16 "
                             "{%0,%1,%2,%3}, [%4];"
                             : "=r"(af[i][0]), "=r"(af[i][1]),
                               "=r"(af[i][2]), "=r"(af[i][3])
                             : "r"(addr));
            }
#pragma unroll
            for (int j = 0; j < 4; j++) {
                int l = lane & 15;
                int r = kk * 16 + l;
                int cc = wn * 4 + j;
                int unit = r * 8 + (cc ^ (r & 7));
                unsigned addr = bb + unit * 16;
                asm volatile("ldmatrix.sync.aligned.m8n8.x2.trans.shared.b16 "
                             "{%0,%1}, [%2];"
                             : "=r"(bf[j][0]), "=r"(bf[j][1])
                             : "r"(addr));
            }
#pragma unroll
            for (int i = 0; i < 2; i++)
#pragma unroll
                for (int j = 0; j < 4; j++)
                    mma16816(c[i][j], af[i], bf[j]);
        }
        __syncthreads();
    }

    // ---- epilogue: fp16 h store + fused logit reduction ----------------------
    int grp = lane >> 2, tq = lane & 3;
    float as0[4], as1[4], ad0[4], ad1[4];
#pragma unroll
    for (int j = 0; j < 4; j++) {
        int col = wn * 32 + j * 8 + 2 * tq;
        as0[j] = asrc[head * CPH + col];     as1[j] = asrc[head * CPH + col + 1];
        ad0[j] = adst[head * CPH + col];     ad1[j] = adst[head * CPH + col + 1];
    }

#pragma unroll
    for (int i = 0; i < 2; i++) {
        int lr0 = wm * 32 + i * 16 + grp;
        int lr1 = lr0 + 8;
        int r0 = mblk + lr0;
        int r1 = mblk + lr1;
        float ps0 = 0.f, pd0 = 0.f, ps1 = 0.f, pd1 = 0.f;
#pragma unroll
        for (int j = 0; j < 4; j++) {
            ps0 = fmaf(c[i][j][0], as0[j], fmaf(c[i][j][1], as1[j], ps0));
            pd0 = fmaf(c[i][j][0], ad0[j], fmaf(c[i][j][1], ad1[j], pd0));
            ps1 = fmaf(c[i][j][2], as0[j], fmaf(c[i][j][3], as1[j], ps1));
            pd1 = fmaf(c[i][j][2], ad0[j], fmaf(c[i][j][3], ad1[j], pd1));
            int gcol = head * 64 + wn * 32 + j * 8 + 2 * tq;
            if (r0 < N)
                g_hh[(long)r0 * HC2 + (gcol >> 1)] =
                    __floats2half2_rn(c[i][j][0], c[i][j][1]);
            if (r1 < N)
                g_hh[(long)r1 * HC2 + (gcol >> 1)] =
                    __floats2half2_rn(c[i][j][2], c[i][j][3]);
        }
#pragma unroll
        for (int o = 1; o < 4; o <<= 1) {
            ps0 += __shfl_xor_sync(0xffffffffu, ps0, o);
            pd0 += __shfl_xor_sync(0xffffffffu, pd0, o);
            ps1 += __shfl_xor_sync(0xffffffffu, ps1, o);
            pd1 += __shfl_xor_sync(0xffffffffu, pd1, o);
        }
        if (tq == 0 && wn == 0) {
            part_s[lr0] = ps0; part_d[lr0] = pd0;
            part_s[lr1] = ps1; part_d[lr1] = pd1;
        }
        __syncthreads();
        if (tq == 0 && wn == 1) {
            if (r0 < N) {
                g_als[r0 * HEADS + head] = ps0 + part_s[lr0];
                g_ald[r0 * HEADS + head] = pd0 + part_d[lr0];
            }
            if (r1 < N) {
                g_als[r1 * HEADS + head] = ps1 + part_s[lr1];
                g_ald[r1 * HEADS + head] = pd1 + part_d[lr1];
            }
        }
        __syncthreads();
    }
}

__device__ __forceinline__ float leaky(float v) {
    return v > 0.f ? v : NEG_SLOPE * v;
}

// ---------------- fused GAT aggregation + bias + ReLU + LN + GCN proj ---------
// TWO warps per dst node (alternating 32-edge tiles), merged via smem.
// Lane covers 8 channels; gather pipelined + batch-8; merge then warp-0 epilogue.
__global__ void __launch_bounds__(128) k_gat(const float* __restrict__ bgat,
                                             const float* __restrict__ gamma,
                                             const float* __restrict__ beta,
                                             const float* __restrict__ wgcn,
                                             int N) {
    __shared__ float4 p_sm[4][32];
    __shared__ int    src_sm[4][32];
    __shared__ float  acc_sm[2][32][8];   // odd warp's accumulators
    __shared__ float  z_sm[4][4];         // [warp][head] z totals
    int w = threadIdx.x >> 5, lane = threadIdx.x & 31;
    int pair = w >> 1, sub = w & 1;
    int d = blockIdx.x * 2 + pair;
    bool active = (d < N);
    int head = lane >> 3;
    int row0 = 0, row1 = 0;
    float4 aldv = make_float4(0.f, 0.f, 0.f, 0.f);
    if (active) {
        row0 = g_off[d];
        row1 = g_off[d + 1];
        aldv = *(const float4*)(g_ald + d * HEADS);
    }

    float acc[8];
#pragma unroll
    for (int j = 0; j < 8; j++) acc[j] = 0.f;
    float zloc[4] = {0.f, 0.f, 0.f, 0.f};

    const __half2* hhp = g_hh;
    int tstart = row0 + sub * 32;        // this warp: tiles tstart, tstart+64, ...

    // prefetch this warp's tile 0
    int s_nx = 0;
    float4 av_nx = make_float4(0.f, 0.f, 0.f, 0.f);
    if (tstart < row1) {
        int cnt0 = min(32, row1 - tstart);
        if (lane < cnt0) {
            s_nx = g_esrc[tstart + lane];
            av_nx = *(const float4*)(g_als + s_nx * HEADS);
        }
    }

    for (int t0 = tstart; t0 < row1; t0 += 64) {
        int cnt = min(32, row1 - t0);
        if (lane < cnt) {
            float p0 = __expf(leaky(av_nx.x + aldv.x));
            float p1 = __expf(leaky(av_nx.y + aldv.y));
            float p2 = __expf(leaky(av_nx.z + aldv.z));
            float p3 = __expf(leaky(av_nx.w + aldv.w));
            p_sm[w][lane] = make_float4(p0, p1, p2, p3);
            src_sm[w][lane] = s_nx;
            zloc[0] += p0; zloc[1] += p1; zloc[2] += p2; zloc[3] += p3;
        }
        __syncwarp();

        // prefetch next tile (stride 64)
        int t1 = t0 + 64;
        if (t1 < row1) {
            int c2 = min(32, row1 - t1);
            if (lane < c2) {
                s_nx = g_esrc[t1 + lane];
                av_nx = *(const float4*)(g_als + s_nx * HEADS);
            }
        }

        int e = 0;
        for (; e + 8 <= cnt; e += 8) {
            uint4 hv[8];
            float pv[8];
#pragma unroll
            for (int u = 0; u < 8; u++) {
                int s = src_sm[w][e + u];
                hv[u] = *(const uint4*)(hhp + (long)s * HC2 + lane * 4);
                pv[u] = ((const float*)&p_sm[w][e + u])[head];
            }
#pragma unroll
            for (int u = 0; u < 8; u++) {
                float p = pv[u];
                float2 f0 = __half22float2(*(__half2*)&hv[u].x);
                float2 f1 = __half22float2(*(__half2*)&hv[u].y);
                float2 f2 = __half22float2(*(__half2*)&hv[u].z);
                float2 f3 = __half22float2(*(__half2*)&hv[u].w);
                acc[0] = fmaf(p, f0.x, acc[0]); acc[1] = fmaf(p, f0.y, acc[1]);
                acc[2] = fmaf(p, f1.x, acc[2]); acc[3] = fmaf(p, f1.y, acc[3]);
                acc[4] = fmaf(p, f2.x, acc[4]); acc[5] = fmaf(p, f2.y, acc[5]);
                acc[6] = fmaf(p, f3.x, acc[6]); acc[7] = fmaf(p, f3.y, acc[7]);
            }
        }
        for (; e < cnt; e++) {
            int s = src_sm[w][e];
            uint4 hv = *(const uint4*)(hhp + (long)s * HC2 + lane * 4);
            float p = ((const float*)&p_sm[w][e])[head];
            float2 f0 = __half22float2(*(__half2*)&hv.x);
            float2 f1 = __half22float2(*(__half2*)&hv.y);
            float2 f2 = __half22float2(*(__half2*)&hv.z);
            float2 f3 = __half22float2(*(__half2*)&hv.w);
            acc[0] = fmaf(p, f0.x, acc[0]); acc[1] = fmaf(p, f0.y, acc[1]);
            acc[2] = fmaf(p, f1.x, acc[2]); acc[3] = fmaf(p, f1.y, acc[3]);
            acc[4] = fmaf(p, f2.x, acc[4]); acc[5] = fmaf(p, f2.y, acc[5]);
            acc[6] = fmaf(p, f3.x, acc[6]); acc[7] = fmaf(p, f3.y, acc[7]);
        }
        __syncwarp();
    }

    // ---- per-warp z totals ----
#pragma unroll
    for (int o = 16; o > 0; o >>= 1) {
#pragma unroll
        for (int h = 0; h < 4; h++)
            zloc[h] += __shfl_xor_sync(0xffffffffu, zloc[h], o);
    }
    if (lane < 4) z_sm[w][lane] = zloc[lane];

    // odd warp deposits accumulators
    if (sub == 1) {
#pragma unroll
        for (int j = 0; j < 8; j++) acc_sm[pair][lane][j] = acc[j];
    }
    __syncthreads();

    if (sub == 1 || !active) return;

    // even warp: merge + epilogue
    float z = z_sm[2 * pair][head] + z_sm[2 * pair + 1][head];
#pragma unroll
    for (int j = 0; j < 8; j++) acc[j] += acc_sm[pair][lane][j];
    float zinv = 1.f / z;

    int ch = lane * 8;
    float4 b0 = *(const float4*)(bgat + ch);
    float4 b1 = *(const float4*)(bgat + ch + 4);
    float v[8];
    v[0] = fmaxf(fmaf(acc[0], zinv, b0.x), 0.f);
    v[1] = fmaxf(fmaf(acc[1], zinv, b0.y), 0.f);
    v[2] = fmaxf(fmaf(acc[2], zinv, b0.z), 0.f);
    v[3] = fmaxf(fmaf(acc[3], zinv, b0.w), 0.f);
    v[4] = fmaxf(fmaf(acc[4], zinv, b1.x), 0.f);
    v[5] = fmaxf(fmaf(acc[5], zinv, b1.y), 0.f);
    v[6] = fmaxf(fmaf(acc[6], zinv, b1.z), 0.f);
    v[7] = fmaxf(fmaf(acc[7], zinv, b1.w), 0.f);

    float s1 = 0.f, s2 = 0.f;
#pragma unroll
    for (int j = 0; j < 8; j++) { s1 += v[j]; s2 = fmaf(v[j], v[j], s2); }
#pragma unroll
    for (int o = 16; o > 0; o >>= 1) {
        s1 += __shfl_xor_sync(0xffffffffu, s1, o);
        s2 += __shfl_xor_sync(0xffffffffu, s2, o);
    }
    float mu = s1 * (1.f / 256.f);
    float var = s2 * (1.f / 256.f) - mu * mu;
    float rs = rsqrtf(var + LN_EPS);

    float4 gm0 = *(const float4*)(gamma + ch);
    float4 gm1 = *(const float4*)(gamma + ch + 4);
    float4 bt0 = *(const float4*)(beta + ch);
    float4 bt1 = *(const float4*)(beta + ch + 4);
    float4 wg0 = *(const float4*)(wgcn + ch);
    float4 wg1 = *(const float4*)(wgcn + ch + 4);
    float gmv[8] = {gm0.x, gm0.y, gm0.z, gm0.w, gm1.x, gm1.y, gm1.z, gm1.w};
    float btv[8] = {bt0.x, bt0.y, bt0.z, bt0.w, bt1.x, bt1.y, bt1.z, bt1.w};
    float wgv[8] = {wg0.x, wg0.y, wg0.z, wg0.w, wg1.x, wg1.y, wg1.z, wg1.w};
    float g = 0.f;
#pragma unroll
    for (int j = 0; j < 8; j++) {
        float a = fmaf((v[j] - mu) * rs, gmv[j], btv[j]);
        g = fmaf(a, wgv[j], g);
    }
#pragma unroll
    for (int o = 16; o > 0; o >>= 1) g += __shfl_xor_sync(0xffffffffu, g, o);

    if (lane == 0)
        g_dh[d] = make_float2(rsqrtf((float)(row1 - row0)), g);
}

// ---------------- GCN aggregation: warp per node (+ g_deg re-zero) ------------
__global__ void k_gcn(const float* __restrict__ bgcn, float* __restrict__ out, int N) {
    int gi = blockIdx.x * 128 + threadIdx.x;   // 320000 threads >= N
    if (gi < N) g_deg[gi] = 0;                 // zero for the NEXT call
    int d = blockIdx.x * 4 + (threadIdx.x >> 5);
    int lane = threadIdx.x & 31;
    if (d >= N) return;
    int row0 = g_off[d], row1 = g_off[d + 1];
    float sum = 0.f;
    for (int i = row0 + lane; i < row1; i += 32) {
        float2 dh = g_dh[g_esrc[i]];
        sum = fmaf(dh.x, dh.y, sum);
    }
#pragma unroll
    for (int o = 16; o > 0; o >>= 1) sum += __shfl_down_sync(0xffffffffu, sum, o);
    if (lane == 0) out[d] = bgcn[0] + g_dh[d].x * sum;
}

// ---------------- launch ------------------------------------------------------
extern "C" void kernel_launch(void* const* d_in, const int* in_sizes, int n_in,
                              void* d_out, int out_size) {
    const float* x     = (const float*)d_in[0];
    const int*   ei    = (const int*)  d_in[1];
    const float* Wgat  = (const float*)d_in[2];
    const float* asrc  = (const float*)d_in[3];
    const float* adst  = (const float*)d_in[4];
    const float* bgat  = (const float*)d_in[5];
    const float* gamma = (const float*)d_in[6];
    const float* beta  = (const float*)d_in[7];
    const float* wgcn  = (const float*)d_in[8];
    const float* bgcn  = (const float*)d_in[9];
    float* out = (float*)d_out;

    int N = in_sizes[0] / IN_C;
    int E = in_sizes[1] / 2;
    const int* src = ei;
    const int* dst = ei + E;

    // one-time side-stream resources (created outside any capture)
    static cudaStream_t s_csr = nullptr;
    static cudaEvent_t  ev_fork = nullptr, ev_join = nullptr;
    if (s_csr == nullptr) {
        cudaStreamCreateWithFlags(&s_csr, cudaStreamNonBlocking);
        cudaEventCreateWithFlags(&ev_fork, cudaEventDisableTiming);
        cudaEventCreateWithFlags(&ev_join, cudaEventDisableTiming);
    }

    // fork: CSR chain on s_csr, fp16 convert + GEMM on the main stream.
    cudaEventRecord(ev_fork, 0);
    cudaStreamWaitEvent(s_csr, ev_fork, 0);

    k_count<<<(E + 1023) / 1024, 256, 0, s_csr>>>(dst, E);
    k_scan<<<1, 1024, 0, s_csr>>>(N);
    k_scatter<<<(E + N + 1023) / 1024, 256, 0, s_csr>>>(src, dst, E, N);
    cudaEventRecord(ev_join, s_csr);

    int total_chunks = N * (IN_C / 8) + (IN_C * HC / 8);
    k_half<<<(total_chunks + 255) / 256, 256>>>(x, Wgat, N);
    dim3 gb(HC / 64, (N + 63) / 64);
    k_gemm<<<gb, 128>>>(asrc, adst, N);

    // join: k_gat needs both CSR and GEMM outputs
    cudaStreamWaitEvent(0, ev_join, 0);
    k_gat<<<(N + 1) / 2, 128>>>(bgat, gamma, beta, wgcn, N);
    k_gcn<<<(N + 3) / 4, 128>>>(bgcn, out, N);
}

// round 16
// speedup vs baseline: 1.1212x; 1.1212x over previous
#include <cuda_runtime.h>
#include <cuda_fp16.h>

#define IN_C   256
#define HC     256
#define HEADS  4
#define CPH    64
#define HC2    128          // half2 count per row
#define NMAX   10000
#define EMAX   320000
#define ETMAX  (EMAX + NMAX)
#define NEG_SLOPE 0.2f
#define LN_EPS 1e-5f

// ---------------- scratch (static device memory; no allocations) -------------
__device__ __align__(16) __half2 g_hh[NMAX * HC2]; // GAT features (fp16 pairs)
__device__ __align__(16) __half  g_xh[NMAX * IN_C]; // X in fp16
__device__ __align__(16) __half  g_wh[IN_C * HC];   // W_gat in fp16 (k-major)
__device__ float  g_als[NMAX * HEADS];
__device__ float  g_ald[NMAX * HEADS];
__device__ __align__(16) int g_deg[NMAX];          // zero at load + re-zeroed by k_gcn
__device__ int    g_off[NMAX + 1];
__device__ int    g_cur[NMAX];
__device__ int    g_esrc[ETMAX];       // CSR by dst: src node of each in-edge
__device__ float2 g_dh[NMAX];          // {dinv, h2} packed

// ---------------- CSR construction -------------------------------------------
__global__ void k_count(const int* __restrict__ dst, int E) {
    int i0 = (blockIdx.x * blockDim.x + threadIdx.x) * 4;
    if (i0 + 3 < E) {
        int4 d4 = *(const int4*)(dst + i0);
        atomicAdd(&g_deg[d4.x], 1);
        atomicAdd(&g_deg[d4.y], 1);
        atomicAdd(&g_deg[d4.z], 1);
        atomicAdd(&g_deg[d4.w], 1);
    } else {
        for (int j = 0; j < 4; j++) {
            int i = i0 + j;
            if (i < E) atomicAdd(&g_deg[dst[i]], 1);
        }
    }
}

// single-block exclusive scan of (g_deg + 1) -> g_off / g_cur, 4 elems/thread
__global__ void k_scan(int N) {
    __shared__ int warp_sums[32];
    __shared__ int carry_s;
    int tid = threadIdx.x;
    int lane = tid & 31, wid = tid >> 5;
    if (tid == 0) carry_s = 0;
    __syncthreads();
    for (int base = 0; base < N; base += 4096) {
        int i0 = base + tid * 4;
        int v0 = 0, v1 = 0, v2 = 0, v3 = 0;
        if (i0 + 3 < N) {
            int4 dv = *(const int4*)&g_deg[i0];
            v0 = dv.x + 1; v1 = dv.y + 1; v2 = dv.z + 1; v3 = dv.w + 1;
        } else {
            if (i0     < N) v0 = g_deg[i0]     + 1;
            if (i0 + 1 < N) v1 = g_deg[i0 + 1] + 1;
            if (i0 + 2 < N) v2 = g_deg[i0 + 2] + 1;
            if (i0 + 3 < N) v3 = g_deg[i0 + 3] + 1;
        }
        int v = v0 + v1 + v2 + v3;
        int incl = v;
#pragma unroll
        for (int s = 1; s < 32; s <<= 1) {
            int t = __shfl_up_sync(0xffffffffu, incl, s);
            if (lane >= s) incl += t;
        }
        if (lane == 31) warp_sums[wid] = incl;
        __syncthreads();
        if (wid == 0) {
            int w = warp_sums[lane];
#pragma unroll
            for (int s = 1; s < 32; s <<= 1) {
                int t = __shfl_up_sync(0xffffffffu, w, s);
                if (lane >= s) w += t;
            }
            warp_sums[lane] = w;
        }
        __syncthreads();
        int warp_base = (wid > 0) ? warp_sums[wid - 1] : 0;
        int c = carry_s;
        int incl_blk = warp_base + incl;
        int e0 = c + incl_blk - v;
        int e1 = e0 + v0, e2 = e1 + v1, e3 = e2 + v2;
        if (i0     < N) { g_off[i0]     = e0; g_cur[i0]     = e0; if (i0     == N - 1) g_off[N] = e1; }
        if (i0 + 1 < N) { g_off[i0 + 1] = e1; g_cur[i0 + 1] = e1; if (i0 + 1 == N - 1) g_off[N] = e2; }
        if (i0 + 2 < N) { g_off[i0 + 2] = e2; g_cur[i0 + 2] = e2; if (i0 + 2 == N - 1) g_off[N] = e3; }
        if (i0 + 3 < N) { g_off[i0 + 3] = e3; g_cur[i0 + 3] = e3; if (i0 + 3 == N - 1) g_off[N] = e3 + v3; }
        __syncthreads();
        if (tid == 1023) carry_s = c + incl_blk;
        __syncthreads();
    }
}

__global__ void k_scatter(const int* __restrict__ src, const int* __restrict__ dst,
                          int E, int N) {
    int i0 = (blockIdx.x * blockDim.x + threadIdx.x) * 4;
    if (i0 + 3 < E) {
        int4 s4 = *(const int4*)(src + i0);
        int4 d4 = *(const int4*)(dst + i0);
        int p0 = atomicAdd(&g_cur[d4.x], 1);
        int p1 = atomicAdd(&g_cur[d4.y], 1);
        int p2 = atomicAdd(&g_cur[d4.z], 1);
        int p3 = atomicAdd(&g_cur[d4.w], 1);
        g_esrc[p0] = s4.x; g_esrc[p1] = s4.y;
        g_esrc[p2] = s4.z; g_esrc[p3] = s4.w;
    } else {
        for (int j = 0; j < 4; j++) {
            int i = i0 + j;
            if (i >= E + N) break;
            int d, s;
            if (i < E) { d = dst[i]; s = src[i]; }
            else       { d = i - E;  s = i - E;  }   // self loop
            int pos = atomicAdd(&g_cur[d], 1);
            g_esrc[pos] = s;
        }
    }
}

// ---------------- fp32 -> fp16 convert for X and W ----------------------------
// Grid-stride, 4 chunks/thread: independent coalesced LDG.128 pairs (MLP 8).
__device__ __forceinline__ void conv8(int c, const float* __restrict__ X,
                                      const float* __restrict__ W, int nx) {
    const float* sp;
    __half* dp;
    if (c < nx) {
        sp = X + (long)c * 8;
        dp = g_xh + (long)c * 8;
    } else {
        int u = c - nx;
        if (u >= IN_C * HC / 8) return;
        sp = W + (long)u * 8;
        dp = g_wh + (long)u * 8;
    }
    float4 a = *(const float4*)sp;
    float4 b = *(const float4*)(sp + 4);
    __half2 h[4];
    h[0] = __floats2half2_rn(a.x, a.y);
    h[1] = __floats2half2_rn(a.z, a.w);
    h[2] = __floats2half2_rn(b.x, b.y);
    h[3] = __floats2half2_rn(b.z, b.w);
    *(uint4*)dp = *(uint4*)h;
}

__global__ void k_half(const float* __restrict__ X, const float* __restrict__ W, int N) {
    int t = blockIdx.x * 256 + threadIdx.x;
    int stride = gridDim.x * 256;
    int nx = N * (IN_C / 8);
    conv8(t,              X, W, nx);
    conv8(t + stride,     X, W, nx);
    conv8(t + 2 * stride, X, W, nx);
    conv8(t + 3 * stride, X, W, nx);
}

// ---------------- tensor-core GEMM + fused logits + fp16 h store --------------
__device__ __forceinline__ void mma16816(float* c, const unsigned* a, const unsigned* b) {
    asm volatile("mma.sync.aligned.m16n8k16.row.col.f32.f16.f16.f32 "
                 "{%0,%1,%2,%3}, {%4,%5,%6,%7}, {%8,%9}, {%0,%1,%2,%3};"
                 : "+f"(c[0]), "+f"(c[1]), "+f"(c[2]), "+f"(c[3])
                 : "r"(a[0]), "r"(a[1]), "r"(a[2]), "r"(a[3]),
                   "r"(b[0]), "r"(b[1]));
}

__device__ __forceinline__ void cp16(unsigned dst, const void* src, int src_sz) {
    asm volatile("cp.async.cg.shared.global [%0], [%1], 16, %2;"
                 :: "r"(dst), "l"(__cvta_generic_to_global(src)), "r"(src_sz));
}

__global__ void __launch_bounds__(128) k_gemm(const float* __restrict__ asrc,
                                              const float* __restrict__ adst,
                                              int N) {
    __shared__ __align__(16) __half As[2][64 * 64];
    __shared__ __align__(16) __half Bs[2][64 * 64];
    __shared__ float part_s[64], part_d[64];
    int tid = threadIdx.x;
    int lane = tid & 31, w = tid >> 5;
    int wm = w >> 1, wn = w & 1;
    int head = blockIdx.x;
    int mblk = blockIdx.y * 64;
    unsigned asb = (unsigned)__cvta_generic_to_shared(&As[0][0]);
    unsigned bsb = (unsigned)__cvta_generic_to_shared(&Bs[0][0]);

    int lr = tid >> 1;
    int lcu = (tid & 1) * 4;
    int arow = mblk + lr;
    int asz = (arow < N) ? 16 : 0;
    const __half* pa = g_xh + (long)min(arow, N - 1) * IN_C + lcu * 8;
    const __half* pb = g_wh + (long)lr * HC + head * 64 + lcu * 8;

    float c[2][4][4];
#pragma unroll
    for (int i = 0; i < 2; i++)
#pragma unroll
        for (int j = 0; j < 4; j++)
#pragma unroll
            for (int q = 0; q < 4; q++) c[i][j][q] = 0.f;

    auto load_slice = [&](int s, int buf) {
        unsigned ab = asb + buf * 8192;
        unsigned bb = bsb + buf * 8192;
#pragma unroll
        for (int u = 0; u < 4; u++) {
            int cc = lcu + u;
            int unit = lr * 8 + (cc ^ (lr & 7));
            cp16(ab + unit * 16, pa + s * 64 + u * 8, asz);
            cp16(bb + unit * 16, pb + (long)s * 64 * HC + u * 8, 16);
        }
    };

    load_slice(0, 0);
    asm volatile("cp.async.commit_group;");

    for (int s = 0; s < 4; s++) {
        if (s < 3) {
            load_slice(s + 1, (s + 1) & 1);
            asm volatile("cp.async.commit_group;");
            asm volatile("cp.async.wait_group 1;");
        } else {
            asm volatile("cp.async.wait_group 0;");
        }
        __syncthreads();

        unsigned ab = asb + (s & 1) * 8192;
        unsigned bb = bsb + (s & 1) * 8192;
#pragma unroll
        for (int kk = 0; kk < 4; kk++) {
            unsigned af[2][4], bf[4][2];
#pragma unroll
            for (int i = 0; i < 2; i++) {
                int r = wm * 32 + i * 16 + (lane & 15);
                int cc = 2 * kk + (lane >> 4);
                int unit = r * 8 + (cc ^ (r & 7));
                unsigned addr = ab + unit * 16;
                asm volatile("ldmatrix.sync.aligned.m8n8.x4.shared.b16 "
                             "{%0,%1,%2,%3}, [%4];"
                             : "=r"(af[i][0]), "=r"(af[i][1]),
                               "=r"(af[i][2]), "=r"(af[i][3])
                             : "r"(addr));
            }
#pragma unroll
            for (int j = 0; j < 4; j++) {
                int l = lane & 15;
                int r = kk * 16 + l;
                int cc = wn * 4 + j;
                int unit = r * 8 + (cc ^ (r & 7));
                unsigned addr = bb + unit * 16;
                asm volatile("ldmatrix.sync.aligned.m8n8.x2.trans.shared.b16 "
                             "{%0,%1}, [%2];"
                             : "=r"(bf[j][0]), "=r"(bf[j][1])
                             : "r"(addr));
            }
#pragma unroll
            for (int i = 0; i < 2; i++)
#pragma unroll
                for (int j = 0; j < 4; j++)
                    mma16816(c[i][j], af[i], bf[j]);
        }
        __syncthreads();
    }

    // ---- epilogue: fp16 h store + fused logit reduction ----------------------
    int grp = lane >> 2, tq = lane & 3;
    float as0[4], as1[4], ad0[4], ad1[4];
#pragma unroll
    for (int j = 0; j < 4; j++) {
        int col = wn * 32 + j * 8 + 2 * tq;
        as0[j] = asrc[head * CPH + col];     as1[j] = asrc[head * CPH + col + 1];
        ad0[j] = adst[head * CPH + col];     ad1[j] = adst[head * CPH + col + 1];
    }

#pragma unroll
    for (int i = 0; i < 2; i++) {
        int lr0 = wm * 32 + i * 16 + grp;
        int lr1 = lr0 + 8;
        int r0 = mblk + lr0;
        int r1 = mblk + lr1;
        float ps0 = 0.f, pd0 = 0.f, ps1 = 0.f, pd1 = 0.f;
#pragma unroll
        for (int j = 0; j < 4; j++) {
            ps0 = fmaf(c[i][j][0], as0[j], fmaf(c[i][j][1], as1[j], ps0));
            pd0 = fmaf(c[i][j][0], ad0[j], fmaf(c[i][j][1], ad1[j], pd0));
            ps1 = fmaf(c[i][j][2], as0[j], fmaf(c[i][j][3], as1[j], ps1));
            pd1 = fmaf(c[i][j][2], ad0[j], fmaf(c[i][j][3], ad1[j], pd1));
            int gcol = head * 64 + wn * 32 + j * 8 + 2 * tq;
            if (r0 < N)
                g_hh[(long)r0 * HC2 + (gcol >> 1)] =
                    __floats2half2_rn(c[i][j][0], c[i][j][1]);
            if (r1 < N)
                g_hh[(long)r1 * HC2 + (gcol >> 1)] =
                    __floats2half2_rn(c[i][j][2], c[i][j][3]);
        }
#pragma unroll
        for (int o = 1; o < 4; o <<= 1) {
            ps0 += __shfl_xor_sync(0xffffffffu, ps0, o);
            pd0 += __shfl_xor_sync(0xffffffffu, pd0, o);
            ps1 += __shfl_xor_sync(0xffffffffu, ps1, o);
            pd1 += __shfl_xor_sync(0xffffffffu, pd1, o);
        }
        if (tq == 0 && wn == 0) {
            part_s[lr0] = ps0; part_d[lr0] = pd0;
            part_s[lr1] = ps1; part_d[lr1] = pd1;
        }
        __syncthreads();
        if (tq == 0 && wn == 1) {
            if (r0 < N) {
                g_als[r0 * HEADS + head] = ps0 + part_s[lr0];
                g_ald[r0 * HEADS + head] = pd0 + part_d[lr0];
            }
            if (r1 < N) {
                g_als[r1 * HEADS + head] = ps1 + part_s[lr1];
                g_ald[r1 * HEADS + head] = pd1 + part_d[lr1];
            }
        }
        __syncthreads();
    }
}

__device__ __forceinline__ float leaky(float v) {
    return v > 0.f ? v : NEG_SLOPE * v;
}

// ---------------- fused GAT aggregation + bias + ReLU + LN + GCN proj ---------
// One WARP per dst node (round-14 version: best measured). Pipelined prefetch
// of next tile's indices+logit rows; batch-8 gather.
__global__ void __launch_bounds__(128) k_gat(const float* __restrict__ bgat,
                                             const float* __restrict__ gamma,
                                             const float* __restrict__ beta,
                                             const float* __restrict__ wgcn,
                                             int N) {
    __shared__ float4 p_sm[4][32];
    __shared__ int    src_sm[4][32];
    int w = threadIdx.x >> 5, lane = threadIdx.x & 31;
    int d = blockIdx.x * 4 + w;
    if (d >= N) return;
    int head = lane >> 3;                 // 8 lanes per head
    int row0 = g_off[d], row1 = g_off[d + 1];

    float4 aldv = *(const float4*)(g_ald + d * HEADS);

    float acc[8];
#pragma unroll
    for (int j = 0; j < 8; j++) acc[j] = 0.f;
    float zloc[4] = {0.f, 0.f, 0.f, 0.f};

    const __half2* hhp = g_hh;

    // prefetch tile 0
    int s_nx = 0;
    float4 av_nx = make_float4(0.f, 0.f, 0.f, 0.f);
    {
        int cnt0 = min(32, row1 - row0);
        if (lane < cnt0) {
            s_nx = g_esrc[row0 + lane];
            av_nx = *(const float4*)(g_als + s_nx * HEADS);
        }
    }

    for (int t0 = row0; t0 < row1; t0 += 32) {
        int cnt = min(32, row1 - t0);
        if (lane < cnt) {
            float p0 = __expf(leaky(av_nx.x + aldv.x));
            float p1 = __expf(leaky(av_nx.y + aldv.y));
            float p2 = __expf(leaky(av_nx.z + aldv.z));
            float p3 = __expf(leaky(av_nx.w + aldv.w));
            p_sm[w][lane] = make_float4(p0, p1, p2, p3);
            src_sm[w][lane] = s_nx;
            zloc[0] += p0; zloc[1] += p1; zloc[2] += p2; zloc[3] += p3;
        }
        __syncwarp();

        // prefetch NEXT tile's indices + logit rows (hidden under gather)
        int t1 = t0 + 32;
        if (t1 < row1) {
            int c2 = min(32, row1 - t1);
            if (lane < c2) {
                s_nx = g_esrc[t1 + lane];
                av_nx = *(const float4*)(g_als + s_nx * HEADS);
            }
        }

        int e = 0;
        for (; e + 8 <= cnt; e += 8) {
            uint4 hv[8];
            float pv[8];
#pragma unroll
            for (int u = 0; u < 8; u++) {
                int s = src_sm[w][e + u];
                hv[u] = *(const uint4*)(hhp + (long)s * HC2 + lane * 4);
                pv[u] = ((const float*)&p_sm[w][e + u])[head];
            }
#pragma unroll
            for (int u = 0; u < 8; u++) {
                float p = pv[u];
                float2 f0 = __half22float2(*(__half2*)&hv[u].x);
                float2 f1 = __half22float2(*(__half2*)&hv[u].y);
                float2 f2 = __half22float2(*(__half2*)&hv[u].z);
                float2 f3 = __half22float2(*(__half2*)&hv[u].w);
                acc[0] = fmaf(p, f0.x, acc[0]); acc[1] = fmaf(p, f0.y, acc[1]);
                acc[2] = fmaf(p, f1.x, acc[2]); acc[3] = fmaf(p, f1.y, acc[3]);
                acc[4] = fmaf(p, f2.x, acc[4]); acc[5] = fmaf(p, f2.y, acc[5]);
                acc[6] = fmaf(p, f3.x, acc[6]); acc[7] = fmaf(p, f3.y, acc[7]);
            }
        }
        for (; e < cnt; e++) {
            int s = src_sm[w][e];
            uint4 hv = *(const uint4*)(hhp + (long)s * HC2 + lane * 4);
            float p = ((const float*)&p_sm[w][e])[head];
            float2 f0 = __half22float2(*(__half2*)&hv.x);
            float2 f1 = __half22float2(*(__half2*)&hv.y);
            float2 f2 = __half22float2(*(__half2*)&hv.z);
            float2 f3 = __half22float2(*(__half2*)&hv.w);
            acc[0] = fmaf(p, f0.x, acc[0]); acc[1] = fmaf(p, f0.y, acc[1]);
            acc[2] = fmaf(p, f1.x, acc[2]); acc[3] = fmaf(p, f1.y, acc[3]);
            acc[4] = fmaf(p, f2.x, acc[4]); acc[5] = fmaf(p, f2.y, acc[5]);
            acc[6] = fmaf(p, f3.x, acc[6]); acc[7] = fmaf(p, f3.y, acc[7]);
        }
        __syncwarp();
    }

    // ---- softmax denominators across lanes ----
#pragma unroll
    for (int o = 16; o > 0; o >>= 1) {
#pragma unroll
        for (int h = 0; h < 4; h++)
            zloc[h] += __shfl_xor_sync(0xffffffffu, zloc[h], o);
    }
    float zinv = 1.f / zloc[head];

    // ---- bias + ReLU ----
    int ch = lane * 8;
    float4 b0 = *(const float4*)(bgat + ch);
    float4 b1 = *(const float4*)(bgat + ch + 4);
    float v[8];
    v[0] = fmaxf(fmaf(acc[0], zinv, b0.x), 0.f);
    v[1] = fmaxf(fmaf(acc[1], zinv, b0.y), 0.f);
    v[2] = fmaxf(fmaf(acc[2], zinv, b0.z), 0.f);
    v[3] = fmaxf(fmaf(acc[3], zinv, b0.w), 0.f);
    v[4] = fmaxf(fmaf(acc[4], zinv, b1.x), 0.f);
    v[5] = fmaxf(fmaf(acc[5], zinv, b1.y), 0.f);
    v[6] = fmaxf(fmaf(acc[6], zinv, b1.z), 0.f);
    v[7] = fmaxf(fmaf(acc[7], zinv, b1.w), 0.f);

    // ---- LayerNorm stats ----
    float s1 = 0.f, s2 = 0.f;
#pragma unroll
    for (int j = 0; j < 8; j++) { s1 += v[j]; s2 = fmaf(v[j], v[j], s2); }
#pragma unroll
    for (int o = 16; o > 0; o >>= 1) {
        s1 += __shfl_xor_sync(0xffffffffu, s1, o);
        s2 += __shfl_xor_sync(0xffffffffu, s2, o);
    }
    float mu = s1 * (1.f / 256.f);
    float var = s2 * (1.f / 256.f) - mu * mu;
    float rs = rsqrtf(var + LN_EPS);

    // ---- LN affine + W_gcn projection ----
    float4 gm0 = *(const float4*)(gamma + ch);
    float4 gm1 = *(const float4*)(gamma + ch + 4);
    float4 bt0 = *(const float4*)(beta + ch);
    float4 bt1 = *(const float4*)(beta + ch + 4);
    float4 wg0 = *(const float4*)(wgcn + ch);
    float4 wg1 = *(const float4*)(wgcn + ch + 4);
    float gmv[8] = {gm0.x, gm0.y, gm0.z, gm0.w, gm1.x, gm1.y, gm1.z, gm1.w};
    float btv[8] = {bt0.x, bt0.y, bt0.z, bt0.w, bt1.x, bt1.y, bt1.z, bt1.w};
    float wgv[8] = {wg0.x, wg0.y, wg0.z, wg0.w, wg1.x, wg1.y, wg1.z, wg1.w};
    float g = 0.f;
#pragma unroll
    for (int j = 0; j < 8; j++) {
        float a = fmaf((v[j] - mu) * rs, gmv[j], btv[j]);
        g = fmaf(a, wgv[j], g);
    }
#pragma unroll
    for (int o = 16; o > 0; o >>= 1) g += __shfl_xor_sync(0xffffffffu, g, o);

    if (lane == 0)
        g_dh[d] = make_float2(rsqrtf((float)(row1 - row0)), g);
}

// ---------------- GCN aggregation: warp per node (+ g_deg re-zero) ------------
__global__ void k_gcn(const float* __restrict__ bgcn, float* __restrict__ out, int N) {
    int gi = blockIdx.x * 128 + threadIdx.x;   // 320000 threads >= N
    if (gi < N) g_deg[gi] = 0;                 // zero for the NEXT call
    int d = blockIdx.x * 4 + (threadIdx.x >> 5);
    int lane = threadIdx.x & 31;
    if (d >= N) return;
    int row0 = g_off[d], row1 = g_off[d + 1];
    float sum = 0.f;
    for (int i = row0 + lane; i < row1; i += 32) {
        float2 dh = g_dh[g_esrc[i]];
        sum = fmaf(dh.x, dh.y, sum);
    }
#pragma unroll
    for (int o = 16; o > 0; o >>= 1) sum += __shfl_down_sync(0xffffffffu, sum, o);
    if (lane == 0) out[d] = bgcn[0] + g_dh[d].x * sum;
}

// ---------------- launch ------------------------------------------------------
extern "C" void kernel_launch(void* const* d_in, const int* in_sizes, int n_in,
                              void* d_out, int out_size) {
    const float* x     = (const float*)d_in[0];
    const int*   ei    = (const int*)  d_in[1];
    const float* Wgat  = (const float*)d_in[2];
    const float* asrc  = (const float*)d_in[3];
    const float* adst  = (const float*)d_in[4];
    const float* bgat  = (const float*)d_in[5];
    const float* gamma = (const float*)d_in[6];
    const float* beta  = (const float*)d_in[7];
    const float* wgcn  = (const float*)d_in[8];
    const float* bgcn  = (const float*)d_in[9];
    float* out = (float*)d_out;

    int N = in_sizes[0] / IN_C;
    int E = in_sizes[1] / 2;
    const int* src = ei;
    const int* dst = ei + E;

    // one-time side-stream resources (created outside any capture)
    static cudaStream_t s_csr = nullptr;
    static cudaEvent_t  ev_fork = nullptr, ev_join = nullptr;
    if (s_csr == nullptr) {
        cudaStreamCreateWithFlags(&s_csr, cudaStreamNonBlocking);
        cudaEventCreateWithFlags(&ev_fork, cudaEventDisableTiming);
        cudaEventCreateWithFlags(&ev_join, cudaEventDisableTiming);
    }

    // fork: CSR chain on s_csr, fp16 convert + GEMM on the main stream.
    cudaEventRecord(ev_fork, 0);
    cudaStreamWaitEvent(s_csr, ev_fork, 0);

    k_count<<<(E + 1023) / 1024, 256, 0, s_csr>>>(dst, E);
    k_scan<<<1, 1024, 0, s_csr>>>(N);
    k_scatter<<<(E + N + 1023) / 1024, 256, 0, s_csr>>>(src, dst, E, N);
    cudaEventRecord(ev_join, s_csr);

    int total_chunks = N * (IN_C / 8) + (IN_C * HC / 8);
    int half_threads = (total_chunks + 3) / 4;
    k_half<<<(half_threads + 255) / 256, 256>>>(x, Wgat, N);
    dim3 gb(HC / 64, (N + 63) / 64);
    k_gemm<<<gb, 128>>>(asrc, adst, N);

    // join: k_gat needs both CSR and GEMM outputs
    cudaStreamWaitEvent(0, ev_join, 0);
    k_gat<<<(N + 3) / 4, 128>>>(bgat, gamma, beta, wgcn, N);
    k_gcn<<<(N + 3) / 4, 128>>>(bgcn, out, N);
}